// round 7
// baseline (speedup 1.0000x reference)
#include <cuda_runtime.h>

// Problem constants
#define NB 4096
#define NT 512
#define NC 4
#define NH 32
#define NO 3

// Layout: 32-thread blocks (1 warp). Warp handles 2 batch rows,
// 16 lanes per row; lane owns (h_2g, h_2g+1) and w_hh rows 2g, 2g+1.
// h exchanged through a tiny double-buffered smem tile (broadcast LDS).
#define ROWS_PER_WARP 2
#define NBLOCKS (NB / ROWS_PER_WARP)   // 2048

// smem h tile: 2 rows x 36 floats (32 h + 4 pad -> row 1 starts at bank 4,
// so each broadcast LDS.v2.u64 has 2 distinct conflict-free addresses).
#define HROW 36
#define HBUF (ROWS_PER_WARP * HROW)    // 72 floats per buffer

__device__ __forceinline__ unsigned long long pk2(float lo, float hi) {
    unsigned long long d;
    asm("mov.b64 %0, {%1, %2};" : "=l"(d) : "f"(lo), "f"(hi));
    return d;
}
__device__ __forceinline__ void upk2(unsigned long long v, float& lo, float& hi) {
    asm("mov.b64 {%0, %1}, %2;" : "=f"(lo), "=f"(hi) : "l"(v));
}
// Packed dual-FMA (FFMA2 in SASS): 2 MACs per issue.
__device__ __forceinline__ unsigned long long fma2(unsigned long long a,
                                                   unsigned long long b,
                                                   unsigned long long c) {
    unsigned long long d;
    asm("fma.rn.f32x2 %0, %1, %2, %3;" : "=l"(d) : "l"(a), "l"(b), "l"(c));
    return d;
}
__device__ __forceinline__ unsigned long long add2(unsigned long long a,
                                                   unsigned long long b) {
    unsigned long long d;
    asm("add.rn.f32x2 %0, %1, %2;" : "=l"(d) : "l"(a), "l"(b));
    return d;
}
__device__ __forceinline__ void lds_2x64(unsigned addr, unsigned long long& a,
                                         unsigned long long& b) {
    asm volatile("ld.shared.v2.u64 {%0, %1}, [%2];" : "=l"(a), "=l"(b) : "r"(addr));
}
__device__ __forceinline__ void sts_64(unsigned addr, unsigned long long v) {
    asm volatile("st.shared.u64 [%0], %1;" :: "r"(addr), "l"(v) : "memory");
}

__global__ void __launch_bounds__(32)
rnn_fused_kernel(const float* __restrict__ seq,
                 const float* __restrict__ w_ih,
                 const float* __restrict__ w_hh,
                 const float* __restrict__ b_ih,
                 const float* __restrict__ b_hh,
                 const float* __restrict__ fc_w,
                 const float* __restrict__ fc_b,
                 float* __restrict__ out) {
    __shared__ float hs[2 * HBUF];

    const int lane = threadIdx.x;        // 0..31
    const int g    = lane & 15;          // lane within row group
    const int half = lane >> 4;          // row within warp (0..1)
    const int row  = blockIdx.x * ROWS_PER_WARP + half;
    const int j0 = 2 * g, j1 = 2 * g + 1;

    // ---- one-time weights into registers, k-packed pairs (k=2p, 2p+1) ----
    unsigned long long wA[NH / 2], wB[NH / 2];
    {
        const float2* wpA = (const float2*)(w_hh + j0 * NH);
        const float2* wpB = (const float2*)(w_hh + j1 * NH);
#pragma unroll
        for (int p = 0; p < NH / 2; p++) {
            const float2 fa = wpA[p];
            const float2 fb = wpB[p];
            wA[p] = pk2(fa.x, fa.y);
            wB[p] = pk2(fb.x, fb.y);
        }
    }
    const unsigned long long wiA0 = pk2(w_ih[j0 * NC + 0], w_ih[j0 * NC + 1]);
    const unsigned long long wiA1 = pk2(w_ih[j0 * NC + 2], w_ih[j0 * NC + 3]);
    const unsigned long long wiB0 = pk2(w_ih[j1 * NC + 0], w_ih[j1 * NC + 1]);
    const unsigned long long wiB1 = pk2(w_ih[j1 * NC + 2], w_ih[j1 * NC + 3]);

    // bias folded as (bias, 0): the end-of-step horizontal add counts it once
    const unsigned long long biasA = pk2(b_ih[j0] + b_hh[j0], 0.0f);
    const unsigned long long biasB = pk2(b_ih[j1] + b_hh[j1], 0.0f);

    // smem addresses
    const unsigned hbase = (unsigned)__cvta_generic_to_shared(hs);
    const unsigned myrow = hbase + half * (HROW * 4);   // buffer 0, own row
    const unsigned mywr  = myrow + g * 8;               // own 8B write slot

    // seq for this row: 16 B / step, broadcast across the row's 16 lanes
    // (2 distinct addresses per warp, L1tex dedup). 2-step register prefetch.
    const float4* sp = (const float4*)(seq + (size_t)row * (NT * NC));
    float4 s0 = sp[0];
    float4 s1 = sp[1];

    // h(t=0) = 0 in buffer 0
    sts_64(mywr, 0ULL);
    __syncwarp();

    float a = 0.0f, b = 0.0f;   // lane's current h pair (live after each step)

    for (int t = 0; t < NT; t++) {
        const int par = t & 1;
        const unsigned rdrow  = myrow + par * (HBUF * 4);        // read buf[par]
        const unsigned wrslot = mywr + (par ^ 1) * (HBUF * 4);   // write buf[par^1]

        const float4 cs = s0;
        s0 = s1;
        const int tn = (t + 2 < NT) ? (t + 2) : (NT - 1);
        s1 = sp[tn];

        const unsigned long long sv = pk2(cs.x, cs.y);
        const unsigned long long sw = pk2(cs.z, cs.w);

        // x_proj seeds (independent of h gather)
        unsigned long long accA0 = fma2(sv, wiA0, biasA);
        unsigned long long accB0 = fma2(sv, wiB0, biasB);
        unsigned long long accA1 = fma2(sw, wiA1, 0ULL);
        unsigned long long accB1 = fma2(sw, wiB1, 0ULL);

        // gather all 32 h of own row: 8 broadcast LDS.v2.u64 (2 distinct
        // addresses per warp, conflict-free by row padding).
        // Pair p=2i feeds the *0 chains, p=2i+1 the *1 chains.
#pragma unroll
        for (int i = 0; i < NH / 4; i++) {
            unsigned long long h0, h1;
            lds_2x64(rdrow + i * 16, h0, h1);
            accA0 = fma2(wA[2 * i],     h0, accA0);
            accB0 = fma2(wB[2 * i],     h0, accB0);
            accA1 = fma2(wA[2 * i + 1], h1, accA1);
            accB1 = fma2(wB[2 * i + 1], h1, accB1);
        }

        // horizontal reduce + relu + publish
        float aLo, aHi, bLo, bHi;
        upk2(add2(accA0, accA1), aLo, aHi);
        upk2(add2(accB0, accB1), bLo, bHi);
        a = fmaxf(aLo + aHi, 0.0f);
        b = fmaxf(bLo + bHi, 0.0f);

        sts_64(wrslot, pk2(a, b));
        __syncwarp();
    }

    // ---- FC head: per-lane partials over (h_j0, h_j1), width-16 reduction ----
    float po[NO];
#pragma unroll
    for (int o = 0; o < NO; o++)
        po[o] = fmaf(a, fc_w[o * NH + j0], b * fc_w[o * NH + j1]);
#pragma unroll
    for (int off = 8; off >= 1; off >>= 1) {
#pragma unroll
        for (int o = 0; o < NO; o++)
            po[o] += __shfl_xor_sync(0xffffffffu, po[o], off, 16);
    }
    if (g == 0) {
#pragma unroll
        for (int o = 0; o < NO; o++)
            out[row * NO + o] = po[o] + fc_b[o];
    }
}

extern "C" void kernel_launch(void* const* d_in, const int* in_sizes, int n_in,
                              void* d_out, int out_size) {
    const float* seq  = (const float*)d_in[0];
    const float* w_ih = (const float*)d_in[1];
    const float* w_hh = (const float*)d_in[2];
    const float* b_ih = (const float*)d_in[3];
    const float* b_hh = (const float*)d_in[4];
    const float* fc_w = (const float*)d_in[5];
    const float* fc_b = (const float*)d_in[6];
    float* out = (float*)d_out;

    rnn_fused_kernel<<<NBLOCKS, 32>>>(seq, w_ih, w_hh, b_ih, b_hh,
                                      fc_w, fc_b, out);
}

// round 8
// speedup vs baseline: 1.1562x; 1.1562x over previous
#include <cuda_runtime.h>

// Problem constants
#define NB 4096
#define NT 512
#define NC 4
#define NH 32
#define NO 3

// Layout: 32-thread blocks (1 warp). Warp handles 8 batch rows.
// Lane l: q = l&7 owns j-quad {4q..4q+3} (weights in regs, SHARED by the
// lane's two rows); s = l>>3 picks the row pair (2s, 2s+1).
#define ROWS_PER_WARP 8
#define NBLOCKS (NB / ROWS_PER_WARP)   // 512

// smem h tile: double-buffered, 8 rows x 36 floats (32 h + 4 pad).
// Row r starts at byte 144*r; mod-128 offsets {0,16,32,...,112} -> every
// broadcast LDS.v2.u64 (4 distinct row addresses) is bank-conflict-free.
#define HROW 36
#define HBUF (ROWS_PER_WARP * HROW)    // 288 floats per buffer

__device__ __forceinline__ unsigned long long pk2(float lo, float hi) {
    unsigned long long d;
    asm("mov.b64 %0, {%1, %2};" : "=l"(d) : "f"(lo), "f"(hi));
    return d;
}
__device__ __forceinline__ void upk2(unsigned long long v, float& lo, float& hi) {
    asm("mov.b64 {%0, %1}, %2;" : "=f"(lo), "=f"(hi) : "l"(v));
}
// Packed dual-FMA (FFMA2 in SASS): 2 MACs per issue.
__device__ __forceinline__ unsigned long long fma2(unsigned long long a,
                                                   unsigned long long b,
                                                   unsigned long long c) {
    unsigned long long d;
    asm("fma.rn.f32x2 %0, %1, %2, %3;" : "=l"(d) : "l"(a), "l"(b), "l"(c));
    return d;
}
__device__ __forceinline__ unsigned long long add2(unsigned long long a,
                                                   unsigned long long b) {
    unsigned long long d;
    asm("add.rn.f32x2 %0, %1, %2;" : "=l"(d) : "l"(a), "l"(b));
    return d;
}
__device__ __forceinline__ void lds_2x64(unsigned addr, unsigned long long& a,
                                         unsigned long long& b) {
    asm volatile("ld.shared.v2.u64 {%0, %1}, [%2];" : "=l"(a), "=l"(b) : "r"(addr));
}
__device__ __forceinline__ void sts_v4(unsigned addr, float a, float b, float c, float d) {
    asm volatile("st.shared.v4.b32 [%0], {%1, %2, %3, %4};"
                 :: "r"(addr), "f"(a), "f"(b), "f"(c), "f"(d) : "memory");
}

__global__ void __launch_bounds__(32)
rnn_fused_kernel(const float* __restrict__ seq,
                 const float* __restrict__ w_ih,
                 const float* __restrict__ w_hh,
                 const float* __restrict__ b_ih,
                 const float* __restrict__ b_hh,
                 const float* __restrict__ fc_w,
                 const float* __restrict__ fc_b,
                 float* __restrict__ out) {
    __shared__ float hs[2 * HBUF];

    const int lane = threadIdx.x;        // 0..31
    const int q    = lane & 7;           // j-quad owner
    const int s    = lane >> 3;          // row-pair selector (0..3)
    const int rA_l = 2 * s;              // local row A
    const int rB_l = 2 * s + 1;          // local row B
    const int rowA = blockIdx.x * ROWS_PER_WARP + rA_l;
    const int rowB = rowA + 1;
    const int jb   = 4 * q;              // first owned hidden index

    // ---- one-time weights into registers (shared by the lane's 2 rows) ----
    unsigned long long w2[4][NH / 2];
#pragma unroll
    for (int jj = 0; jj < 4; jj++) {
        const float2* wp = (const float2*)(w_hh + (jb + jj) * NH);
#pragma unroll
        for (int p = 0; p < NH / 2; p++) {
            const float2 f = wp[p];
            w2[jj][p] = pk2(f.x, f.y);
        }
    }
    unsigned long long wiE[4], wiO[4], bias[4];
#pragma unroll
    for (int jj = 0; jj < 4; jj++) {
        const int j = jb + jj;
        wiE[jj]  = pk2(w_ih[j * NC + 0], w_ih[j * NC + 1]);
        wiO[jj]  = pk2(w_ih[j * NC + 2], w_ih[j * NC + 3]);
        bias[jj] = pk2(b_ih[j] + b_hh[j], 0.0f);   // counted once by horizontal add
    }

    // smem addresses
    const unsigned hbase = (unsigned)__cvta_generic_to_shared(hs);
    const unsigned rowAb = hbase + rA_l * (HROW * 4);
    const unsigned rowBb = hbase + rB_l * (HROW * 4);
    const unsigned wrA0  = rowAb + q * 16;
    const unsigned wrB0  = rowBb + q * 16;

    // seq pointers for the lane's two rows; 2-step register prefetch.
    const float4* spA = (const float4*)(seq + (size_t)rowA * (NT * NC));
    const float4* spB = (const float4*)(seq + (size_t)rowB * (NT * NC));
    float4 sA0 = spA[0], sA1 = spA[1];
    float4 sB0 = spB[0], sB1 = spB[1];

    // h(t=0) = 0 in buffer 0
    sts_v4(wrA0, 0.f, 0.f, 0.f, 0.f);
    sts_v4(wrB0, 0.f, 0.f, 0.f, 0.f);
    __syncwarp();

    float vA0, vA1, vA2, vA3;   // row A current h quad
    float vB0, vB1, vB2, vB3;   // row B current h quad

    for (int t = 0; t < NT; t++) {
        const int par = t & 1;
        const unsigned rdA = rowAb + par * (HBUF * 4);
        const unsigned rdB = rowBb + par * (HBUF * 4);
        const unsigned wrA = wrA0 + (par ^ 1) * (HBUF * 4);
        const unsigned wrB = wrB0 + (par ^ 1) * (HBUF * 4);

        const float4 cA = sA0;  sA0 = sA1;
        const float4 cB = sB0;  sB0 = sB1;
        const int tn = (t + 2 < NT) ? (t + 2) : (NT - 1);
        sA1 = spA[tn];
        sB1 = spB[tn];

        const unsigned long long svA = pk2(cA.x, cA.y);
        const unsigned long long swA = pk2(cA.z, cA.w);
        const unsigned long long svB = pk2(cB.x, cB.y);
        const unsigned long long swB = pk2(cB.z, cB.w);

        // x_proj seeds, both rows (independent of h gather)
        unsigned long long aE0 = fma2(svA, wiE[0], bias[0]);
        unsigned long long aE1 = fma2(svA, wiE[1], bias[1]);
        unsigned long long aE2 = fma2(svA, wiE[2], bias[2]);
        unsigned long long aE3 = fma2(svA, wiE[3], bias[3]);
        unsigned long long aO0 = fma2(swA, wiO[0], 0ULL);
        unsigned long long aO1 = fma2(swA, wiO[1], 0ULL);
        unsigned long long aO2 = fma2(swA, wiO[2], 0ULL);
        unsigned long long aO3 = fma2(swA, wiO[3], 0ULL);
        unsigned long long bE0 = fma2(svB, wiE[0], bias[0]);
        unsigned long long bE1 = fma2(svB, wiE[1], bias[1]);
        unsigned long long bE2 = fma2(svB, wiE[2], bias[2]);
        unsigned long long bE3 = fma2(svB, wiE[3], bias[3]);
        unsigned long long bO0 = fma2(swB, wiO[0], 0ULL);
        unsigned long long bO1 = fma2(swB, wiO[1], 0ULL);
        unsigned long long bO2 = fma2(swB, wiO[2], 0ULL);
        unsigned long long bO3 = fma2(swB, wiO[3], 0ULL);

        // gather both rows' h (8+8 broadcast LDS, 4 distinct addrs each,
        // conflict-free); pair p=2i feeds E chains, p=2i+1 feeds O chains.
#pragma unroll
        for (int i = 0; i < NH / 4; i++) {
            unsigned long long hA0, hA1, hB0, hB1;
            lds_2x64(rdA + i * 16, hA0, hA1);
            lds_2x64(rdB + i * 16, hB0, hB1);
            aE0 = fma2(w2[0][2 * i], hA0, aE0);
            aE1 = fma2(w2[1][2 * i], hA0, aE1);
            aE2 = fma2(w2[2][2 * i], hA0, aE2);
            aE3 = fma2(w2[3][2 * i], hA0, aE3);
            bE0 = fma2(w2[0][2 * i], hB0, bE0);
            bE1 = fma2(w2[1][2 * i], hB0, bE1);
            bE2 = fma2(w2[2][2 * i], hB0, bE2);
            bE3 = fma2(w2[3][2 * i], hB0, bE3);
            aO0 = fma2(w2[0][2 * i + 1], hA1, aO0);
            aO1 = fma2(w2[1][2 * i + 1], hA1, aO1);
            aO2 = fma2(w2[2][2 * i + 1], hA1, aO2);
            aO3 = fma2(w2[3][2 * i + 1], hA1, aO3);
            bO0 = fma2(w2[0][2 * i + 1], hB1, bO0);
            bO1 = fma2(w2[1][2 * i + 1], hB1, bO1);
            bO2 = fma2(w2[2][2 * i + 1], hB1, bO2);
            bO3 = fma2(w2[3][2 * i + 1], hB1, bO3);
        }

        // horizontal reduce + relu, both rows
        float lo, hi;
        upk2(add2(aE0, aO0), lo, hi); vA0 = fmaxf(lo + hi, 0.0f);
        upk2(add2(aE1, aO1), lo, hi); vA1 = fmaxf(lo + hi, 0.0f);
        upk2(add2(aE2, aO2), lo, hi); vA2 = fmaxf(lo + hi, 0.0f);
        upk2(add2(aE3, aO3), lo, hi); vA3 = fmaxf(lo + hi, 0.0f);
        upk2(add2(bE0, bO0), lo, hi); vB0 = fmaxf(lo + hi, 0.0f);
        upk2(add2(bE1, bO1), lo, hi); vB1 = fmaxf(lo + hi, 0.0f);
        upk2(add2(bE2, bO2), lo, hi); vB2 = fmaxf(lo + hi, 0.0f);
        upk2(add2(bE3, bO3), lo, hi); vB3 = fmaxf(lo + hi, 0.0f);

        // publish both rows' quads for next step
        sts_v4(wrA, vA0, vA1, vA2, vA3);
        sts_v4(wrB, vB0, vB1, vB2, vB3);
        __syncwarp();
    }

    // ---- FC head: per-lane partials over owned 4 h, width-8 xor reduce ----
    float pa[NO], pb[NO];
#pragma unroll
    for (int o = 0; o < NO; o++) {
        const float* fw = fc_w + o * NH + jb;
        pa[o] = fmaf(vA0, fw[0], fmaf(vA1, fw[1], fmaf(vA2, fw[2], vA3 * fw[3])));
        pb[o] = fmaf(vB0, fw[0], fmaf(vB1, fw[1], fmaf(vB2, fw[2], vB3 * fw[3])));
    }
#pragma unroll
    for (int off = 4; off >= 1; off >>= 1) {
#pragma unroll
        for (int o = 0; o < NO; o++) {
            pa[o] += __shfl_xor_sync(0xffffffffu, pa[o], off, 8);
            pb[o] += __shfl_xor_sync(0xffffffffu, pb[o], off, 8);
        }
    }
    if (q == 0) {
#pragma unroll
        for (int o = 0; o < NO; o++) {
            out[rowA * NO + o] = pa[o] + fc_b[o];
            out[rowB * NO + o] = pb[o] + fc_b[o];
        }
    }
}

extern "C" void kernel_launch(void* const* d_in, const int* in_sizes, int n_in,
                              void* d_out, int out_size) {
    const float* seq  = (const float*)d_in[0];
    const float* w_ih = (const float*)d_in[1];
    const float* w_hh = (const float*)d_in[2];
    const float* b_ih = (const float*)d_in[3];
    const float* b_hh = (const float*)d_in[4];
    const float* fc_w = (const float*)d_in[5];
    const float* fc_b = (const float*)d_in[6];
    float* out = (float*)d_out;

    rnn_fused_kernel<<<NBLOCKS, 32>>>(seq, w_ih, w_hh, b_ih, b_hh,
                                      fc_w, fc_b, out);
}

// round 10
// speedup vs baseline: 1.1907x; 1.0298x over previous
#include <cuda_runtime.h>

// Problem constants
#define NB 4096
#define NT 512
#define NC 4
#define NH 32
#define NO 3

// Layout: 32-thread blocks (1 warp). Warp handles 8 batch rows.
// Lane l: q = l&7 owns j-quad {4q..4q+3} (weights in regs, shared by the
// lane's two rows); s = l>>3 picks the row pair (2s, 2s+1).
#define ROWS_PER_WARP 8
#define NBLOCKS (NB / ROWS_PER_WARP)   // 512

// smem h tile: double-buffered, 8 rows x 36 floats (32 h + 4 pad).
// Row r at byte 144*r -> mod-128 offsets {0,32,64,96} (even rows) and
// {16,48,80,112} (odd rows): every broadcast LDS.v2.u64 (4 distinct row
// addresses, 8-way broadcast) is bank-conflict-free.
#define HROW 36
#define HBUF (ROWS_PER_WARP * HROW)    // 288 floats per buffer

__device__ __forceinline__ unsigned long long pk2(float lo, float hi) {
    unsigned long long d;
    asm("mov.b64 %0, {%1, %2};" : "=l"(d) : "f"(lo), "f"(hi));
    return d;
}
__device__ __forceinline__ void upk2(unsigned long long v, float& lo, float& hi) {
    asm("mov.b64 {%0, %1}, %2;" : "=f"(lo), "=f"(hi) : "l"(v));
}
// Packed dual-FMA (FFMA2 in SASS): 2 MACs per issue.
__device__ __forceinline__ unsigned long long fma2(unsigned long long a,
                                                   unsigned long long b,
                                                   unsigned long long c) {
    unsigned long long d;
    asm("fma.rn.f32x2 %0, %1, %2, %3;" : "=l"(d) : "l"(a), "l"(b), "l"(c));
    return d;
}
__device__ __forceinline__ void lds_2x64(unsigned addr, unsigned long long& a,
                                         unsigned long long& b) {
    asm volatile("ld.shared.v2.u64 {%0, %1}, [%2];" : "=l"(a), "=l"(b) : "r"(addr));
}
__device__ __forceinline__ void sts_v4(unsigned addr, float a, float b, float c, float d) {
    asm volatile("st.shared.v4.b32 [%0], {%1, %2, %3, %4};"
                 :: "r"(addr), "f"(a), "f"(b), "f"(c), "f"(d) : "memory");
}

__global__ void __launch_bounds__(32)
rnn_fused_kernel(const float* __restrict__ seq,
                 const float* __restrict__ w_ih,
                 const float* __restrict__ w_hh,
                 const float* __restrict__ b_ih,
                 const float* __restrict__ b_hh,
                 const float* __restrict__ fc_w,
                 const float* __restrict__ fc_b,
                 float* __restrict__ out) {
    __shared__ float hs[2 * HBUF];

    const int lane = threadIdx.x;        // 0..31
    const int q    = lane & 7;           // j-quad owner
    const int s    = lane >> 3;          // row-pair selector (0..3)
    const int rA_l = 2 * s;
    const int rB_l = 2 * s + 1;
    const int rowA = blockIdx.x * ROWS_PER_WARP + rA_l;
    const int rowB = rowA + 1;
    const int jb   = 4 * q;              // first owned hidden index

    // ---- one-time weights into registers (shared by the lane's 2 rows) ----
    unsigned long long w2[4][NH / 2];
#pragma unroll
    for (int jj = 0; jj < 4; jj++) {
        const float2* wp = (const float2*)(w_hh + (jb + jj) * NH);
#pragma unroll
        for (int p = 0; p < NH / 2; p++) {
            const float2 f = wp[p];
            w2[jj][p] = pk2(f.x, f.y);
        }
    }
    unsigned long long wiE[4], wiO[4], bias[4];
#pragma unroll
    for (int jj = 0; jj < 4; jj++) {
        const int j = jb + jj;
        wiE[jj]  = pk2(w_ih[j * NC + 0], w_ih[j * NC + 1]);
        wiO[jj]  = pk2(w_ih[j * NC + 2], w_ih[j * NC + 3]);
        bias[jj] = pk2(b_ih[j] + b_hh[j], 0.0f);   // counted once by horizontal add
    }

    // smem addresses (buffer 0)
    const unsigned hbase = (unsigned)__cvta_generic_to_shared(hs);
    const unsigned rdA0 = hbase + rA_l * (HROW * 4);
    const unsigned rdB0 = hbase + rB_l * (HROW * 4);
    const unsigned wrA0 = rdA0 + q * 16;
    const unsigned wrB0 = rdB0 + q * 16;
    const unsigned BOFF = HBUF * 4;      // byte offset of buffer 1

    // seq pointers for the lane's two rows; 2-step register prefetch.
    const float4* spA = (const float4*)(seq + (size_t)rowA * (NT * NC));
    const float4* spB = (const float4*)(seq + (size_t)rowB * (NT * NC));
    float4 sA0 = spA[0], sA1 = spA[1];
    float4 sB0 = spB[0], sB1 = spB[1];

    // h(t=0) = 0 in buffer 0
    sts_v4(wrA0, 0.f, 0.f, 0.f, 0.f);
    sts_v4(wrB0, 0.f, 0.f, 0.f, 0.f);
    __syncwarp();

    float vA0, vA1, vA2, vA3;   // row A current h quad (live after each step)
    float vB0, vB1, vB2, vB3;   // row B current h quad

    // One RNN step. RD = read-buffer byte offset, WR = write-buffer offset
    // (compile-time constants after unroll-2).
#define RNN_STEP(T, RD, WR)                                                   \
    {                                                                         \
        const float4 cA = sA0;  sA0 = sA1;                                    \
        const float4 cB = sB0;  sB0 = sB1;                                    \
        const int tn = ((T) + 2 < NT) ? ((T) + 2) : (NT - 1);                 \
        sA1 = spA[tn];                                                        \
        sB1 = spB[tn];                                                        \
        const unsigned long long svA = pk2(cA.x, cA.y);                       \
        const unsigned long long swA = pk2(cA.z, cA.w);                       \
        const unsigned long long svB = pk2(cB.x, cB.y);                       \
        const unsigned long long swB = pk2(cB.z, cB.w);                       \
        /* 4 accumulators per row: one 18-deep chain per owned j */           \
        unsigned long long a0 = fma2(svA, wiE[0], bias[0]);                   \
        unsigned long long a1 = fma2(svA, wiE[1], bias[1]);                   \
        unsigned long long a2 = fma2(svA, wiE[2], bias[2]);                   \
        unsigned long long a3 = fma2(svA, wiE[3], bias[3]);                   \
        unsigned long long b0 = fma2(svB, wiE[0], bias[0]);                   \
        unsigned long long b1 = fma2(svB, wiE[1], bias[1]);                   \
        unsigned long long b2 = fma2(svB, wiE[2], bias[2]);                   \
        unsigned long long b3 = fma2(svB, wiE[3], bias[3]);                   \
        a0 = fma2(swA, wiO[0], a0);                                           \
        a1 = fma2(swA, wiO[1], a1);                                           \
        a2 = fma2(swA, wiO[2], a2);                                           \
        a3 = fma2(swA, wiO[3], a3);                                           \
        b0 = fma2(swB, wiO[0], b0);                                           \
        b1 = fma2(swB, wiO[1], b1);                                           \
        b2 = fma2(swB, wiO[2], b2);                                           \
        b3 = fma2(swB, wiO[3], b3);                                           \
        _Pragma("unroll")                                                     \
        for (int m = 0; m < NH / 4; m++) {                                    \
            unsigned long long hA0, hA1, hB0, hB1;                            \
            lds_2x64(rdA0 + (RD) + m * 16, hA0, hA1);                         \
            lds_2x64(rdB0 + (RD) + m * 16, hB0, hB1);                         \
            a0 = fma2(w2[0][2 * m], hA0, a0);                                 \
            a1 = fma2(w2[1][2 * m], hA0, a1);                                 \
            a2 = fma2(w2[2][2 * m], hA0, a2);                                 \
            a3 = fma2(w2[3][2 * m], hA0, a3);                                 \
            b0 = fma2(w2[0][2 * m], hB0, b0);                                 \
            b1 = fma2(w2[1][2 * m], hB0, b1);                                 \
            b2 = fma2(w2[2][2 * m], hB0, b2);                                 \
            b3 = fma2(w2[3][2 * m], hB0, b3);                                 \
            a0 = fma2(w2[0][2 * m + 1], hA1, a0);                             \
            a1 = fma2(w2[1][2 * m + 1], hA1, a1);                             \
            a2 = fma2(w2[2][2 * m + 1], hA1, a2);                             \
            a3 = fma2(w2[3][2 * m + 1], hA1, a3);                             \
            b0 = fma2(w2[0][2 * m + 1], hB1, b0);                             \
            b1 = fma2(w2[1][2 * m + 1], hB1, b1);                             \
            b2 = fma2(w2[2][2 * m + 1], hB1, b2);                             \
            b3 = fma2(w2[3][2 * m + 1], hB1, b3);                             \
        }                                                                     \
        float lo, hi;                                                         \
        upk2(a0, lo, hi); vA0 = fmaxf(lo + hi, 0.0f);                         \
        upk2(a1, lo, hi); vA1 = fmaxf(lo + hi, 0.0f);                         \
        upk2(a2, lo, hi); vA2 = fmaxf(lo + hi, 0.0f);                         \
        upk2(a3, lo, hi); vA3 = fmaxf(lo + hi, 0.0f);                         \
        upk2(b0, lo, hi); vB0 = fmaxf(lo + hi, 0.0f);                         \
        upk2(b1, lo, hi); vB1 = fmaxf(lo + hi, 0.0f);                         \
        upk2(b2, lo, hi); vB2 = fmaxf(lo + hi, 0.0f);                         \
        upk2(b3, lo, hi); vB3 = fmaxf(lo + hi, 0.0f);                         \
        sts_v4(wrA0 + (WR), vA0, vA1, vA2, vA3);                              \
        sts_v4(wrB0 + (WR), vB0, vB1, vB2, vB3);                              \
        __syncwarp();                                                         \
    }

    for (int t = 0; t < NT; t += 2) {
        RNN_STEP(t,     0u,   BOFF);   // read buf0, write buf1
        RNN_STEP(t + 1, BOFF, 0u);     // read buf1, write buf0
    }
#undef RNN_STEP

    // ---- FC head: per-lane partials over owned 4 h, width-8 xor reduce ----
    float pa[NO], pb[NO];
#pragma unroll
    for (int o = 0; o < NO; o++) {
        const float* fw = fc_w + o * NH + jb;
        pa[o] = fmaf(vA0, fw[0], fmaf(vA1, fw[1], fmaf(vA2, fw[2], vA3 * fw[3])));
        pb[o] = fmaf(vB0, fw[0], fmaf(vB1, fw[1], fmaf(vB2, fw[2], vB3 * fw[3])));
    }
#pragma unroll
    for (int off = 4; off >= 1; off >>= 1) {
#pragma unroll
        for (int o = 0; o < NO; o++) {
            pa[o] += __shfl_xor_sync(0xffffffffu, pa[o], off, 8);
            pb[o] += __shfl_xor_sync(0xffffffffu, pb[o], off, 8);
        }
    }
    if (q == 0) {
#pragma unroll
        for (int o = 0; o < NO; o++) {
            out[rowA * NO + o] = pa[o] + fc_b[o];
            out[rowB * NO + o] = pb[o] + fc_b[o];
        }
    }
}

extern "C" void kernel_launch(void* const* d_in, const int* in_sizes, int n_in,
                              void* d_out, int out_size) {
    const float* seq  = (const float*)d_in[0];
    const float* w_ih = (const float*)d_in[1];
    const float* w_hh = (const float*)d_in[2];
    const float* b_ih = (const float*)d_in[3];
    const float* b_hh = (const float*)d_in[4];
    const float* fc_w = (const float*)d_in[5];
    const float* fc_b = (const float*)d_in[6];
    float* out = (float*)d_out;

    rnn_fused_kernel<<<NBLOCKS, 32>>>(seq, w_ih, w_hh, b_ih, b_hh,
                                      fc_w, fc_b, out);
}